// round 13
// baseline (speedup 1.0000x reference)
#include <cuda_runtime.h>
#include <cuda_bf16.h>
#include <cstdint>

typedef unsigned long long ull;

// Problem: x (8,256,128,128) f32 -> out (8,256,64,64) f32
// CARAFE downsample, decomposed:
//   compress: cx[b,h,w,cc] (bf16, px-major) = x * w_comp + b_comp   (tf32 mma GEMM)
//   encoder:  logit = 3x3-s2 conv(cx) * exp(p)                      (tf32 mma, bf16<<16)
//   softmax -> masks; aggregate: 25-tap s2 gather (warp-private, barrier-free)

// ---------------- compress geometry (M=256: 2 rows/block) ----------------
#define C_XP    264
#define C_XSF   8448                 // 32*264
#define C_WBP   36
#define C_WBSF  2304                 // 64*36
#define C_SMEMF (4*C_XSF + 4*C_WBSF + 64)
// ---------------- encoder geometry (bf16 staging) ----------------
#define E_CXP   72
#define E_SLOTS 297
#define E_CXH   (E_SLOTS * E_CXP)    // 21384 halves
#define E_WEP   584
#define E_WEH   (32 * E_WEP)         // 18688 halves
#define E_SMEMB (E_CXH*2 + E_WEH*2 + 128)
// ---------------- aggregate geometry (warp-private stages) ----------------
#define AG_PITCH   40                // floats per staged row (10 aligned quads)
#define AG_ROWS    11
#define AG_CHF     440               // 11*40 floats per channel-stage
#define AG_STAGES  6
#define AG_WARPF   (AG_STAGES * AG_CHF)      // 2640 floats per warp
#define AG_SMEMF   (8 * AG_WARPF)            // 21120 floats = 84480 B
#define AG_CHUNKS  110               // 11 rows * 10 chunks of 16B

// ---- persistent device scratch ----
__device__ float g_wb[64 * 256];
__device__ __nv_bfloat16 g_web[32 * 576];
__device__ float g_bk[32];
__device__ float g_bc[64];
__device__ float g_mask[8 * 25 * 4096];
__device__ __nv_bfloat16 g_cx[8 * 128 * 128 * 64];

__device__ __forceinline__ ull pack2(float a, float b) {
    ull r; asm("mov.b64 %0, {%1, %2};" : "=l"(r) : "f"(a), "f"(b)); return r;
}
__device__ __forceinline__ void unpack2(ull v, float& a, float& b) {
    asm("mov.b64 {%0, %1}, %2;" : "=f"(a), "=f"(b) : "l"(v));
}
#define FMA2(d, a, b) asm("fma.rn.f32x2 %0, %1, %2, %0;" : "+l"(d) : "l"(a), "l"(b))

__device__ __forceinline__ uint32_t f2tf(float f) {
    uint32_t r; asm("cvt.rna.tf32.f32 %0, %1;" : "=r"(r) : "f"(f)); return r;
}
__device__ __forceinline__ void mma_tf32(float* d, const uint32_t* a, uint32_t b0, uint32_t b1) {
    asm volatile("mma.sync.aligned.m16n8k8.row.col.f32.tf32.tf32.f32 "
                 "{%0,%1,%2,%3}, {%4,%5,%6,%7}, {%8,%9}, {%0,%1,%2,%3};"
                 : "+f"(d[0]), "+f"(d[1]), "+f"(d[2]), "+f"(d[3])
                 : "r"(a[0]), "r"(a[1]), "r"(a[2]), "r"(a[3]), "r"(b0), "r"(b1));
}

__device__ __forceinline__ uint32_t smem_u32(const void* p) {
    return (uint32_t)__cvta_generic_to_shared(p);
}
__device__ __forceinline__ void cpa16(uint32_t dst, const void* src) {
    asm volatile("cp.async.ca.shared.global [%0], [%1], 16;" :: "r"(dst), "l"(src));
}
__device__ __forceinline__ void cpa4(uint32_t dst, const void* src) {
    asm volatile("cp.async.ca.shared.global [%0], [%1], 4;" :: "r"(dst), "l"(src));
}
#define CP_COMMIT() asm volatile("cp.async.commit_group;")
template<int N> __device__ __forceinline__ void cp_wait() {
    asm volatile("cp.async.wait_group %0;" :: "n"(N));
}

// ============================================================================
// Kernel 1: prep. 96 blocks x 256 threads.
// ============================================================================
__global__ void prep_kernel(const float* __restrict__ w_comp, const float* __restrict__ b_comp,
                            const float* __restrict__ w_enc, const float* __restrict__ b_enc,
                            const float* __restrict__ power_p) {
    int bid = blockIdx.x, t = threadIdx.x;
    float expP = __expf(power_p[0]);
    if (bid < 64) {
        g_wb[bid * 256 + t] = __uint_as_float(f2tf(w_comp[bid * 256 + t]));
    } else {
        int n = bid - 64;
        for (int i = t; i < 576; i += 256) {
            float v = 0.f;
            if (n < 25) {
                int cc = i & 63, tap = i >> 6;
                v = w_enc[((n * 64 + cc) * 9) + tap] * expP;
            }
            g_web[n * 576 + i] = __float2bfloat16(v);
        }
        if (n == 0 && t < 32) g_bk[t] = (t < 25) ? b_enc[t] * expP : 0.f;
        if (n == 1 && t < 64) g_bc[t] = b_comp[t];
    }
}

// ============================================================================
// Kernel 2: compress GEMM. 512 blocks (2 rows each), 256 threads.
// M=256, N=64, K=256; tf32 m16n8k8; bf16 smem-staged coalesced output.
// ============================================================================
__global__ __launch_bounds__(256) void compress_kernel(const float* __restrict__ x) {
    extern __shared__ __align__(16) float SM[];
    int bid = blockIdx.x;
    int b = bid >> 6, h2 = bid & 63;
    int tid = threadIdx.x;
    int wid = tid >> 5, lane = tid & 31;
    int g = lane >> 2, tig = lane & 3;

    float* XS  = SM;
    float* WBS = SM + 4 * C_XSF;
    float* BC  = SM + 4 * C_XSF + 4 * C_WBSF;

    if (tid < 64) BC[tid] = g_bc[tid];

    uint32_t xsa = smem_u32(XS), wba = smem_u32(WBS);
    const float* xb = x + ((size_t)b * 256) * 16384 + h2 * 256;

    auto fill = [&](int s, int kc) {
        const float* xc = xb + (size_t)(kc * 32) * 16384;
        uint32_t xd = xsa + (uint32_t)s * (C_XSF * 4);
#pragma unroll
        for (int j = 0; j < 8; j++) {
            int idx = tid + j * 256;
            int c = idx >> 6, q = idx & 63;
            cpa16(xd + (uint32_t)(c * C_XP + 4 * q) * 4, xc + (size_t)c * 16384 + 4 * q);
        }
        uint32_t wd = wba + (uint32_t)s * (C_WBSF * 4);
#pragma unroll
        for (int j = 0; j < 2; j++) {
            int idx = tid + j * 256;
            int cc = idx >> 3, q = idx & 7;
            cpa16(wd + (uint32_t)(cc * C_WBP + 4 * q) * 4, g_wb + cc * 256 + kc * 32 + 4 * q);
        }
    };

    float d[2][8][4];
#pragma unroll
    for (int mt = 0; mt < 2; mt++)
#pragma unroll
        for (int nt = 0; nt < 8; nt++)
#pragma unroll
            for (int j = 0; j < 4; j++) d[mt][nt][j] = 0.f;

    fill(0, 0); CP_COMMIT();
    fill(1, 1); CP_COMMIT();
#pragma unroll 1
    for (int i = 0; i < 8; i++) {
        if (i + 2 < 8) fill((i + 2) & 3, i + 2);
        CP_COMMIT();
        cp_wait<2>();
        __syncthreads();

        const float* xs = XS + (i & 3) * C_XSF;
        const uint32_t* wbs = (const uint32_t*)(WBS + (i & 3) * C_WBSF);
#pragma unroll
        for (int k8 = 0; k8 < 4; k8++) {
            int cb = k8 * 8;
            uint32_t a[2][4];
#pragma unroll
            for (int mt = 0; mt < 2; mt++) {
                int pxl = 32 * wid + 16 * mt + g;
                a[mt][0] = f2tf(xs[(cb + tig) * C_XP + pxl]);
                a[mt][1] = f2tf(xs[(cb + tig) * C_XP + pxl + 8]);
                a[mt][2] = f2tf(xs[(cb + tig + 4) * C_XP + pxl]);
                a[mt][3] = f2tf(xs[(cb + tig + 4) * C_XP + pxl + 8]);
            }
#pragma unroll
            for (int nt = 0; nt < 8; nt++) {
                uint32_t b0 = wbs[(8 * nt + g) * C_WBP + cb + tig];
                uint32_t b1 = wbs[(8 * nt + g) * C_WBP + cb + tig + 4];
                mma_tf32(d[0][nt], a[0], b0, b1);
                mma_tf32(d[1][nt], a[1], b0, b1);
            }
        }
    }

    __syncthreads();
    uint32_t* CXT32 = (uint32_t*)SM;
#pragma unroll
    for (int mt = 0; mt < 2; mt++) {
#pragma unroll
        for (int nt = 0; nt < 8; nt++) {
            int pxl = 32 * wid + 16 * mt + g;
            int cc = 8 * nt + 2 * tig;
            float bc0 = BC[cc], bc1 = BC[cc + 1];
            __nv_bfloat162 p0 = __floats2bfloat162_rn(d[mt][nt][0] + bc0, d[mt][nt][1] + bc1);
            __nv_bfloat162 p1 = __floats2bfloat162_rn(d[mt][nt][2] + bc0, d[mt][nt][3] + bc1);
            CXT32[pxl * 32 + (cc >> 1)]       = *(uint32_t*)&p0;
            CXT32[(pxl + 8) * 32 + (cc >> 1)] = *(uint32_t*)&p1;
        }
    }
    __syncthreads();
    const uint4* srcq = (const uint4*)SM;
    uint4* dstq = (uint4*)(g_cx + (size_t)bid * 16384);
#pragma unroll
    for (int j = 0; j < 8; j++)
        dstq[tid + j * 256] = srcq[tid + j * 256];
}

// ============================================================================
// Kernel 3: encoder GEMM + softmax -> g_mask. 512 blocks, 128 threads.
// M=64 px, N=32, K=576. bf16 staging, tf32 mma via <<16.
// ============================================================================
__global__ __launch_bounds__(128) void encoder_kernel() {
    extern __shared__ __align__(16) char SMC[];
    unsigned short* CXS = (unsigned short*)SMC;
    unsigned short* WES = (unsigned short*)(SMC + E_CXH * 2);
    float* BKS = (float*)(SMC + E_CXH * 2 + E_WEH * 2);

    int bid = blockIdx.x;
    int b = bid >> 6, t = bid & 63;
    int w0 = (t & 3) * 16;
    int h0 = (t >> 2) * 4;
    int tid = threadIdx.x;
    int wid = tid >> 5, lane = tid & 31;
    int g = lane >> 2, tig = lane & 3;

    uint32_t* cz = (uint32_t*)CXS;
    for (int i = tid; i < E_CXH / 2; i += 128) cz[i] = 0u;
    if (tid < 32) BKS[tid] = g_bk[tid];
    __syncthreads();

    uint32_t cxa = smem_u32(CXS), wea = smem_u32(WES);
#pragma unroll 4
    for (int j = 0; j < 18; j++) {
        int idx = tid + j * 128;
        int n = idx / 72, q = idx - n * 72;
        cpa16(wea + (uint32_t)(n * E_WEP + 8 * q) * 2, g_web + n * 576 + 8 * q);
    }
#pragma unroll 4
    for (int j = 0; j < 19; j++) {
        int idx = tid + j * 128;
        if (idx < 2376) {
            int slot = idx >> 3, q = idx & 7;
            int r = slot / 33, pi = slot - r * 33;
            int hr = 2 * h0 - 1 + r;
            int wc = 2 * w0 - 1 + pi;
            if (hr >= 0 && hr < 128 && wc >= 0 && wc < 128)
                cpa16(cxa + (uint32_t)(slot * E_CXP + 8 * q) * 2,
                      g_cx + ((size_t)(b * 128 + hr) * 128 + wc) * 64 + 8 * q);
        }
    }
    CP_COMMIT();
    cp_wait<0>();
    __syncthreads();

    float d[4][4];
#pragma unroll
    for (int nt = 0; nt < 4; nt++)
#pragma unroll
        for (int j = 0; j < 4; j++) d[nt][j] = 0.f;

#pragma unroll 1
    for (int tap = 0; tap < 9; tap++) {
        int dy = tap / 3, dx = tap % 3;
        const unsigned short* baseL = CXS + ((2 * wid + dy) * 33 + (2 * g + dx)) * E_CXP;
        const unsigned short* baseH = baseL + 16 * E_CXP;
#pragma unroll
        for (int kc = 0; kc < 8; kc++) {
            int cb = kc * 8;
            uint32_t a[4];
            a[0] = ((uint32_t)baseL[cb + tig]) << 16;
            a[1] = ((uint32_t)baseH[cb + tig]) << 16;
            a[2] = ((uint32_t)baseL[cb + tig + 4]) << 16;
            a[3] = ((uint32_t)baseH[cb + tig + 4]) << 16;
            int ko = tap * 64 + cb + tig;
#pragma unroll
            for (int nt = 0; nt < 4; nt++) {
                uint32_t b0 = ((uint32_t)WES[(8 * nt + g) * E_WEP + ko]) << 16;
                uint32_t b1 = ((uint32_t)WES[(8 * nt + g) * E_WEP + ko + 4]) << 16;
                mma_tf32(d[nt], a, b0, b1);
            }
        }
    }

    int hh = h0 + wid;
#pragma unroll
    for (int half = 0; half < 2; half++) {
        int ww = w0 + g + 8 * half;
        float lg[8];
#pragma unroll
        for (int nt = 0; nt < 4; nt++) {
#pragma unroll
            for (int j = 0; j < 2; j++) {
                int n = 8 * nt + 2 * tig + j;
                float v = d[nt][2 * half + j];
                lg[nt * 2 + j] = (n < 25) ? (v + BKS[n]) : -1e30f;
            }
        }
        float mx = lg[0];
#pragma unroll
        for (int j = 1; j < 8; j++) mx = fmaxf(mx, lg[j]);
        mx = fmaxf(mx, __shfl_xor_sync(0xffffffffu, mx, 1));
        mx = fmaxf(mx, __shfl_xor_sync(0xffffffffu, mx, 2));
        float sum = 0.f;
#pragma unroll
        for (int j = 0; j < 8; j++) { lg[j] = __expf(lg[j] - mx); sum += lg[j]; }
        sum += __shfl_xor_sync(0xffffffffu, sum, 1);
        sum += __shfl_xor_sync(0xffffffffu, sum, 2);
        float inv = 1.f / sum;
#pragma unroll
        for (int nt = 0; nt < 4; nt++) {
#pragma unroll
            for (int j = 0; j < 2; j++) {
                int n = 8 * nt + 2 * tig + j;
                if (n < 25)
                    g_mask[((b * 25 + n) << 12) + (hh << 6) + ww] = lg[nt * 2 + j] * inv;
            }
        }
    }
}

// ============================================================================
// Kernel 4: aggregate, warp-private barrier-free. 512 blocks (8b x 64 tiles of
// 16w x 4h), 256 threads = 8 warps. Warp w owns channels {w, w+8, ...} and 6
// private smem stages (11 rows x 40 cols, origin col = 2*w0-4: 16B-aligned).
// No block barriers in the loop; per-warp cp.async wait + __syncwarp only.
// Lane = pxp(8) x pyq(4); consume = 2x LDS.128 + 1x LDS.64 per row (R10 map).
// Border taps handled by zeroed mask lanes (pad value is 0).
// ============================================================================
__global__ __launch_bounds__(256) void aggregate_kernel(const float* __restrict__ x,
                                                        float* __restrict__ out) {
    extern __shared__ __align__(16) float AG[];
    int bid = blockIdx.x;
    int b = bid >> 6;
    int t = bid & 63;
    int w0 = (t & 3) << 4;
    int h0 = (t >> 2) << 2;
    int tid = threadIdx.x;
    int lane = tid & 31, warp = tid >> 5;
    int pxp = lane & 7, pyq = lane >> 3;
    int h = h0 + pyq;
    int wbase = w0 + 2 * pxp;
    int O = 2 * w0 - 4;                     // 16B-aligned gmem origin

    // zero all stages once (OOB slots stay zero forever)
    for (int i = tid; i < AG_SMEMF; i += 256) AG[i] = 0.f;

    // ---- masks with OOB-tap zeroing (replaces x zero-padding exactly) ----
    ull mp[2][5][3];
#pragma unroll
    for (int e = 0; e < 2; e++) {
        int w = wbase + e;
        float m[25];
#pragma unroll
        for (int k = 0; k < 25; k++)
            m[k] = g_mask[((b * 25 + k) << 12) + (h << 6) + w];
#pragma unroll
        for (int di = 0; di < 5; di++) {
            int r = 2 * h - 2 + di;
            bool rok = (r >= 0) && (r < 128);
            float mv[5];
#pragma unroll
            for (int dj = 0; dj < 5; dj++) {
                int col = 2 * w - 2 + dj;
                mv[dj] = (rok && col >= 0 && col < 128) ? m[di * 5 + dj] : 0.f;
            }
            mp[e][di][0] = pack2(mv[0], mv[1]);
            mp[e][di][1] = pack2(mv[2], mv[3]);
            mp[e][di][2] = pack2(mv[4], 0.f);
        }
    }

    // ---- one-time per-lane fill addressing (4 chunk-slots over 110 chunks) ----
    int goff[4]; uint32_t soff[4]; int mode[4];   // 0=skip, 1=full16B, else 16|bitmask
#pragma unroll
    for (int j = 0; j < 4; j++) {
        int idx = lane + 32 * j;
        mode[j] = 0; goff[j] = 0; soff[j] = 0;
        if (idx < AG_CHUNKS) {
            int r_loc = idx / 10, cq = idx - r_loc * 10;
            int R = 2 * h0 - 2 + r_loc;
            int cs = O + 4 * cq;
            if (R >= 0 && R < 128) {
                int vb = 0;
#pragma unroll
                for (int f = 0; f < 4; f++)
                    if (cs + f >= 0 && cs + f < 128) vb |= 1 << f;
                if (vb == 15) mode[j] = 1;
                else if (vb)  mode[j] = 16 | vb;
            }
            goff[j] = R * 128 + cs;
            soff[j] = (uint32_t)((r_loc * AG_PITCH + 4 * cq) * 4);
        }
    }

    uint32_t wsa = smem_u32(AG) + (uint32_t)(warp * AG_WARPF * 4);
    const float* xb = x + (size_t)b * 256 * 16384;

    auto fill = [&](int c, int s) {
        const float* xc = xb + (size_t)c * 16384;
        uint32_t sb = wsa + (uint32_t)(s * AG_CHF * 4);
#pragma unroll
        for (int j = 0; j < 4; j++) {
            int md = mode[j];
            if (md == 1) {
                cpa16(sb + soff[j], xc + goff[j]);
            } else if (md > 1) {
#pragma unroll
                for (int f = 0; f < 4; f++)
                    if (md & (1 << f)) cpa4(sb + soff[j] + 4 * f, xc + goff[j] + f);
            }
        }
    };

    __syncthreads();   // zeros visible to all warps (once)

    // prologue: 5 stages ahead
#pragma unroll
    for (int p = 0; p < 5; p++) { fill(warp + 8 * p, p); CP_COMMIT(); }

    float* ob = out + (((size_t)b * 256) << 12) + (h << 6) + wbase;

#pragma unroll 1
    for (int i = 0; i < 32; i++) {
        int ip = i + 5;
        if (ip < 32) fill(warp + 8 * ip, ip % 6);
        CP_COMMIT();
        cp_wait<5>();
        __syncwarp();

        // thread's quads start at local float 4*pxp (16B-aligned):
        // slots 4p..4p+3 (qa), 4p+4..4p+7 (qb), 4p+8..4p+9 (d2)
        const float* rp = AG + warp * AG_WARPF + (i % 6) * AG_CHF + 4 * pxp;
        ull accA = 0ull, accB = 0ull;
#pragma unroll
        for (int di = 0; di < 5; di++) {
            const float* rr = rp + (2 * pyq + di) * AG_PITCH;
            ulonglong2 qa = *(const ulonglong2*)(rr);       // floats 0..3
            ulonglong2 qb = *(const ulonglong2*)(rr + 4);   // floats 4..7
            ull d2 = *(const ull*)(rr + 8);                 // floats 8,9
            // e=0 (w=wbase):  cols 2w-2.. -> slots 2,3 | 4,5 | 6,(7)
            FMA2(accA, mp[0][di][0], qa.y);
            FMA2(accA, mp[0][di][1], qb.x);
            FMA2(accA, mp[0][di][2], qb.y);
            // e=1 (w=wbase+1): cols -> slots 4,5 | 6,7 | 8,(9)
            FMA2(accB, mp[1][di][0], qb.x);
            FMA2(accB, mp[1][di][1], qb.y);
            FMA2(accB, mp[1][di][2], d2);
        }
        float a0, a1, b0, b1;
        unpack2(accA, a0, a1);
        unpack2(accB, b0, b1);
        int c = warp + 8 * i;
        *(float2*)(ob + ((size_t)c << 12)) = make_float2(a0 + a1, b0 + b1);
        __syncwarp();
    }
}

// ============================================================================
extern "C" void kernel_launch(void* const* d_in, const int* in_sizes, int n_in,
                              void* d_out, int out_size) {
    const float* x       = (const float*)d_in[0];
    const float* w_comp  = (const float*)d_in[1];
    const float* b_comp  = (const float*)d_in[2];
    const float* w_enc   = (const float*)d_in[3];
    const float* b_enc   = (const float*)d_in[4];
    const float* power_p = (const float*)d_in[5];
    float* out = (float*)d_out;

    cudaFuncSetAttribute(compress_kernel, cudaFuncAttributeMaxDynamicSharedMemorySize,
                         C_SMEMF * 4);
    cudaFuncSetAttribute(encoder_kernel, cudaFuncAttributeMaxDynamicSharedMemorySize,
                         E_SMEMB);
    cudaFuncSetAttribute(aggregate_kernel, cudaFuncAttributeMaxDynamicSharedMemorySize,
                         AG_SMEMF * 4);

    prep_kernel<<<96, 256>>>(w_comp, b_comp, w_enc, b_enc, power_p);
    compress_kernel<<<512, 256, C_SMEMF * 4>>>(x);
    encoder_kernel<<<512, 128, E_SMEMB>>>();
    aggregate_kernel<<<512, 256, AG_SMEMF * 4>>>(x, out);
}